// round 6
// baseline (speedup 1.0000x reference)
#include <cuda_runtime.h>

// ============================================================================
// HistCausalEncoder: B=16, T=64, P=64, IN=256, ACT=64, OUT=256, H=4, concat=1536
//
// z_t = b + Wo*o_t + sum_h Wa_h*a_{t-4+h}   (phase 1, parallel over all t)
//         + sum_h Wz_h*z_{t-4+h}            (phase 2, sequential launches over t)
//
// All GEMMs run fp32 via packed fma.rn.f32x2 (FFMA2, 2 MACs/instr) with
// column-pair-packed accumulators. Weights are pre-transposed into k-major
// scratch (g_Wk for phase 1, g_Wz for phase 2) by a tiny prep kernel.
// Phase 2 accumulates in-place into d_out, so d_out is the recurrence state.
// ============================================================================

// --- weight scratch (device globals: allocation-free scratch) ---
__device__ float g_Wk[512 * 256];   // [k][n], k = [a_{t-4}(64) a_{t-3} a_{t-2} a_{t-1} | o(256)]
__device__ float g_Wz[1024 * 256];  // [k][n], k = [z_{t-4}(256) z_{t-3} z_{t-2} z_{t-1}]

// --- packed-f32x2 helpers ---
__device__ __forceinline__ unsigned long long bcast2(float x) {
    unsigned long long r;
    unsigned int xi = __float_as_uint(x);
    asm("mov.b64 %0, {%1, %2};" : "=l"(r) : "r"(xi), "r"(xi));
    return r;
}
__device__ __forceinline__ void fma2(unsigned long long &d,
                                     unsigned long long a,
                                     unsigned long long b) {
    asm("fma.rn.f32x2 %0, %1, %2, %0;" : "+l"(d) : "l"(a), "l"(b));
}
__device__ __forceinline__ float2 up2(unsigned long long v) {
    float2 f;
    asm("mov.b64 {%0, %1}, %2;" : "=f"(f.x), "=f"(f.y) : "l"(v));
    return f;
}

// ============================================================================
// prep: gather/transpose W (256 x 1536, row-major) into k-major g_Wk / g_Wz
// ============================================================================
__global__ void prep_kernel(const float* __restrict__ W) {
    int idx = blockIdx.x * 256 + threadIdx.x;
    if (idx < 512 * 256) {
        int k = idx >> 8, n = idx & 255;
        int col = (k < 256) ? ((k >> 6) * 320 + 256 + (k & 63))  // a-history slot h=k/64
                            : (1280 + (k - 256));                // o features
        g_Wk[idx] = W[n * 1536 + col];
    } else {
        int idx2 = idx - 512 * 256;
        if (idx2 < 1024 * 256) {
            int k = idx2 >> 8, n = idx2 & 255;
            int col = (k >> 8) * 320 + (k & 255);                // z-history slot h=k/256
            g_Wz[idx2] = W[n * 1536 + col];
        }
    }
}

// ============================================================================
// phase 1: out[b,t,p,:] = bias + [a_{t-4..t-1}, o_t] (512) @ g_Wk (512x256)
// grid (4 colTiles, B*T), 256 thr, CTA tile 64(p) x 64(n), micro 4x4, KC=16
// ============================================================================
__global__ void __launch_bounds__(256) phase1_kernel(
    const float* __restrict__ o, const float* __restrict__ act,
    const float* __restrict__ bias, float* __restrict__ out)
{
    __shared__ __align__(16) float As[2][16 * 68];  // [k][row], pad 68 for bank/align
    __shared__ __align__(16) float Bs[2][16 * 64];  // [k][col]

    const int tid = threadIdx.x;
    const int colbase = blockIdx.x * 64;
    const int bt = blockIdx.y;
    const int b = bt >> 6, t = bt & 63;
    const int rg = tid >> 4, cg = tid & 15;         // micro-tile coords

    unsigned long long acc[4][2];
    #pragma unroll
    for (int r = 0; r < 4; ++r) { acc[r][0] = 0ull; acc[r][1] = 0ull; }

    float ra[4], rb[4];
    const int akk = tid & 15, ar0 = tid >> 4;       // A-load mapping
    const int bcl = tid & 63, bkk = tid >> 6;       // B-load mapping

    auto loadChunk = [&](int cc) {
        const int kbase = cc * 16;
        const int k = kbase + akk;
        if (kbase < 256) {                           // a-history region
            const int h = k >> 6, j = k & 63;        // h uniform per chunk (16|64)
            const int ts = t - 4 + h;
            if (ts >= 0) {
                const float* base = act + (b * 64 + ts) * 4096 + j;   // P*ACT=4096
                #pragma unroll
                for (int q = 0; q < 4; ++q) ra[q] = base[(ar0 + q * 16) * 64];
            } else {
                #pragma unroll
                for (int q = 0; q < 4; ++q) ra[q] = 0.f;
            }
        } else {                                     // o region
            const int i = k - 256;
            const float* base = o + (b * 64 + t) * 16384 + i;          // P*IN=16384
            #pragma unroll
            for (int q = 0; q < 4; ++q) ra[q] = base[(ar0 + q * 16) * 256];
        }
        const float* wb = g_Wk + (kbase + bkk) * 256 + colbase + bcl;
        #pragma unroll
        for (int q = 0; q < 4; ++q) rb[q] = wb[q * 4 * 256];
    };

    auto stsChunk = [&](int buf) {
        #pragma unroll
        for (int q = 0; q < 4; ++q) As[buf][akk * 68 + ar0 + q * 16] = ra[q];
        #pragma unroll
        for (int q = 0; q < 4; ++q) Bs[buf][(bkk + q * 4) * 64 + bcl] = rb[q];
    };

    auto compute = [&](int buf) {
        #pragma unroll
        for (int kk = 0; kk < 16; ++kk) {
            const float4 a4 = *reinterpret_cast<const float4*>(&As[buf][kk * 68 + rg * 4]);
            const ulonglong2 bq = *reinterpret_cast<const ulonglong2*>(&Bs[buf][kk * 64 + cg * 4]);
            unsigned long long a0 = bcast2(a4.x), a1 = bcast2(a4.y);
            unsigned long long a2 = bcast2(a4.z), a3 = bcast2(a4.w);
            fma2(acc[0][0], a0, bq.x); fma2(acc[0][1], a0, bq.y);
            fma2(acc[1][0], a1, bq.x); fma2(acc[1][1], a1, bq.y);
            fma2(acc[2][0], a2, bq.x); fma2(acc[2][1], a2, bq.y);
            fma2(acc[3][0], a3, bq.x); fma2(acc[3][1], a3, bq.y);
        }
    };

    const int NC = 32;                               // K=512 / 16
    loadChunk(0); stsChunk(0);
    loadChunk(1);
    __syncthreads();
    for (int cc = 0; cc < NC; ++cc) {
        const int nb = (cc + 1) & 1;
        if (cc + 1 < NC) stsChunk(nb);               // ra/rb hold chunk cc+1
        if (cc + 2 < NC) loadChunk(cc + 2);          // prefetch next into regs
        compute(cc & 1);
        __syncthreads();
    }

    const int col = colbase + cg * 4;
    const float4 bv = *reinterpret_cast<const float4*>(&bias[col]);
    #pragma unroll
    for (int r = 0; r < 4; ++r) {
        float2 x0 = up2(acc[r][0]);
        float2 x1 = up2(acc[r][1]);
        float4 ov = make_float4(x0.x + bv.x, x0.y + bv.y, x1.x + bv.z, x1.y + bv.w);
        const int row = rg * 4 + r;                  // row == p
        *reinterpret_cast<float4*>(&out[((b * 64 + t) * 64 + row) * 256 + col]) = ov;
    }
}

// ============================================================================
// phase 2 (per t): out[:,t,:,:] += z[t-4..t-1] (K up to 1024) @ g_Wz (1024x256)
// grid (4 colTiles, 32 rowTiles) = 128 CTAs; 256 thr split in two K-halves,
// each half: CTA tile 32(row) x 64(n), micro 4x4, KC=32 per chunk (16/half).
// Smem reduction across halves, then read-modify-write into out.
// ============================================================================
__global__ void __launch_bounds__(256) phase2_kernel(float* __restrict__ out, const int t)
{
    __shared__ __align__(16) float As[2][32 * 36];  // [k][row], pad 36 (144B, 16B-aligned)
    __shared__ __align__(16) float Bs[2][32 * 64];  // [k][col]

    const int tid = threadIdx.x;
    const int colbase = blockIdx.x * 64;
    const int R0 = blockIdx.y * 32;                 // global row base (b,p flattened)
    const int b = R0 >> 6, p0 = R0 & 63;
    const int half = tid >> 7, tl = tid & 127;
    const int rg = tl >> 4, cg = tl & 15;

    const int h0 = (t >= 4) ? 0 : (4 - t);          // first valid history slot
    const int kStart = h0 << 8;
    const int NC = (1024 - kStart) >> 5;            // >= 8 for t >= 1

    unsigned long long acc[4][2];
    #pragma unroll
    for (int r = 0; r < 4; ++r) { acc[r][0] = 0ull; acc[r][1] = 0ull; }

    float ra[4], rb[8];
    const int akk = tid & 31, arr = tid >> 5;
    const int bcl = tid & 63, bkk = tid >> 6;

    auto loadChunk = [&](int cc) {
        const int kbase = kStart + cc * 32;
        const int h = kbase >> 8;                    // uniform per chunk (32|256)
        const int ts = t - 4 + h;                    // >= 0 by construction
        const int i0 = kbase & 255;
        const float* base = out + ((b * 64 + ts) * 64 + p0) * 256 + i0 + akk;
        #pragma unroll
        for (int q = 0; q < 4; ++q) ra[q] = base[(arr + q * 8) * 256];
        const float* wb = g_Wz + (kbase + bkk) * 256 + colbase + bcl;
        #pragma unroll
        for (int q = 0; q < 8; ++q) rb[q] = wb[q * 4 * 256];
    };

    auto stsChunk = [&](int buf) {
        #pragma unroll
        for (int q = 0; q < 4; ++q) As[buf][akk * 36 + arr + q * 8] = ra[q];
        #pragma unroll
        for (int q = 0; q < 8; ++q) Bs[buf][(bkk + q * 4) * 64 + bcl] = rb[q];
    };

    auto compute = [&](int buf) {
        const int k0 = half * 16;
        #pragma unroll
        for (int kk = 0; kk < 16; ++kk) {
            const int kx = k0 + kk;
            const float4 a4 = *reinterpret_cast<const float4*>(&As[buf][kx * 36 + rg * 4]);
            const ulonglong2 bq = *reinterpret_cast<const ulonglong2*>(&Bs[buf][kx * 64 + cg * 4]);
            unsigned long long a0 = bcast2(a4.x), a1 = bcast2(a4.y);
            unsigned long long a2 = bcast2(a4.z), a3 = bcast2(a4.w);
            fma2(acc[0][0], a0, bq.x); fma2(acc[0][1], a0, bq.y);
            fma2(acc[1][0], a1, bq.x); fma2(acc[1][1], a1, bq.y);
            fma2(acc[2][0], a2, bq.x); fma2(acc[2][1], a2, bq.y);
            fma2(acc[3][0], a3, bq.x); fma2(acc[3][1], a3, bq.y);
        }
    };

    loadChunk(0); stsChunk(0);
    loadChunk(1);
    __syncthreads();
    for (int cc = 0; cc < NC; ++cc) {
        const int nb = (cc + 1) & 1;
        if (cc + 1 < NC) stsChunk(nb);
        if (cc + 2 < NC) loadChunk(cc + 2);
        compute(cc & 1);
        __syncthreads();
    }

    // reduce the two K-halves through smem (reuse Bs[0]: 128 thr * 8 u64 = 8 KB)
    unsigned long long* red = reinterpret_cast<unsigned long long*>(&Bs[0][0]);
    if (half == 1) {
        #pragma unroll
        for (int r = 0; r < 4; ++r) {
            red[tl * 8 + r * 2]     = acc[r][0];
            red[tl * 8 + r * 2 + 1] = acc[r][1];
        }
    }
    __syncthreads();
    if (half == 0) {
        const int col = colbase + cg * 4;
        #pragma unroll
        for (int r = 0; r < 4; ++r) {
            float2 m0 = up2(acc[r][0]), m1 = up2(acc[r][1]);
            float2 o0 = up2(red[tl * 8 + r * 2]);
            float2 o1 = up2(red[tl * 8 + r * 2 + 1]);
            const int row = p0 + rg * 4 + r;
            float4* ptr = reinterpret_cast<float4*>(
                &out[((b * 64 + t) * 64 + row) * 256 + col]);
            float4 cur = *ptr;
            cur.x += m0.x + o0.x; cur.y += m0.y + o0.y;
            cur.z += m1.x + o1.x; cur.w += m1.y + o1.y;
            *ptr = cur;
        }
    }
}

// ============================================================================
// launch: prep -> phase1 -> 63 ordered phase2 launches (graph-capturable)
// ============================================================================
extern "C" void kernel_launch(void* const* d_in, const int* in_sizes, int n_in,
                              void* d_out, int out_size)
{
    const float* o_in  = (const float*)d_in[0];   // (16,64,64,256)
    const float* a_in  = (const float*)d_in[1];   // (16,64,64,64)
    const float* W_in  = (const float*)d_in[2];   // (256,1536)
    const float* b_in  = (const float*)d_in[3];   // (256,)
    float* out = (float*)d_out;                   // (16,64,64,256)

    prep_kernel<<<1536, 256>>>(W_in);
    phase1_kernel<<<dim3(4, 1024), 256>>>(o_in, a_in, b_in, out);
    for (int t = 1; t < 64; ++t)                  // t=0 has no recurrence terms
        phase2_kernel<<<dim3(4, 32), 256>>>(out, t);
}

// round 10
// speedup vs baseline: 1.0380x; 1.0380x over previous
#include <cuda_runtime.h>
#include <cuda_bf16.h>
#include <cstdint>

// ============================================================================
// HistCausalEncoder: B=16,T=64,P=64,IN=256,ACT=64,OUT=256,H=4
// phase1 (fp32 FFMA2): z = b + Wo*o_t + sum_h Wa_h*a_{t-4+h}     (parallel)
// phase2 (HMMA bf16-split): z += sum_h Wz_h*z_{t-4+h}             (63 launches)
//   3-term split zh*Wh + zl*Wh + zh*Wl, fp32 accum via mma.sync.m16n8k16.
//   z kept as bf16 hi/lo ring (g_zh/g_zl) so phase2 A-operands are MMA-ready.
// R10 fix vs R9: B-fragment register pairing. ldmatrix.x4 on [n][k] memory
// gives r0=n0-7/k0-7, r1=n8-15/k0-7, r2=n0-7/k8-15, r3=n8-15/k8-15; mma wants
// (b0,b1) = same n-octet, k-halves stacked -> (r[ni&1], r[(ni&1)+2]).
// ============================================================================

__device__ float g_Wk[512 * 256];                           // phase1 W, k-major
__device__ __align__(256) __nv_bfloat16 g_Bh[4][256][256];  // Wz hi, [h][n][k]
__device__ __align__(256) __nv_bfloat16 g_Bl[4][256][256];  // Wz lo
__device__ __align__(256) __nv_bfloat16 g_zh[64][1024][256];// z hi, [t][b*64+p][c]
__device__ __align__(256) __nv_bfloat16 g_zl[64][1024][256];// z lo

// ---------- helpers ----------
__device__ __forceinline__ uint32_t smem_u32(const void* p) {
    uint32_t a;
    asm("{ .reg .u64 t; cvta.to.shared.u64 t, %1; cvt.u32.u64 %0, t; }" : "=r"(a) : "l"(p));
    return a;
}
__device__ __forceinline__ void cp16(uint32_t dst, const void* src) {
    asm volatile("cp.async.cg.shared.global [%0], [%1], 16;" :: "r"(dst), "l"(src) : "memory");
}
__device__ __forceinline__ void cp_commit() { asm volatile("cp.async.commit_group;" ::: "memory"); }
template <int N> __device__ __forceinline__ void cp_wait() {
    asm volatile("cp.async.wait_group %0;" :: "n"(N) : "memory");
}
__device__ __forceinline__ void ldx4(uint32_t (&r)[4], uint32_t a) {
    asm volatile("ldmatrix.sync.aligned.m8n8.x4.shared.b16 {%0,%1,%2,%3}, [%4];"
                 : "=r"(r[0]), "=r"(r[1]), "=r"(r[2]), "=r"(r[3]) : "r"(a));
}
__device__ __forceinline__ void mma16816(float (&d)[4], const uint32_t (&a)[4],
                                         uint32_t b0, uint32_t b1) {
    asm volatile("mma.sync.aligned.m16n8k16.row.col.f32.bf16.bf16.f32 "
                 "{%0,%1,%2,%3}, {%4,%5,%6,%7}, {%8,%9}, {%0,%1,%2,%3};"
                 : "+f"(d[0]), "+f"(d[1]), "+f"(d[2]), "+f"(d[3])
                 : "r"(a[0]), "r"(a[1]), "r"(a[2]), "r"(a[3]), "r"(b0), "r"(b1));
}
__device__ __forceinline__ unsigned long long bcast2(float x) {
    unsigned long long r; unsigned int xi = __float_as_uint(x);
    asm("mov.b64 %0, {%1, %2};" : "=l"(r) : "r"(xi), "r"(xi));
    return r;
}
__device__ __forceinline__ void fma2(unsigned long long &d, unsigned long long a, unsigned long long b) {
    asm("fma.rn.f32x2 %0, %1, %2, %0;" : "+l"(d) : "l"(a), "l"(b));
}
__device__ __forceinline__ float2 up2(unsigned long long v) {
    float2 f; asm("mov.b64 {%0, %1}, %2;" : "=f"(f.x), "=f"(f.y) : "l"(v));
    return f;
}

// ---------- prep ----------
__global__ void prep_kernel(const float* __restrict__ W) {
    int idx = blockIdx.x * 256 + threadIdx.x;       // < 512*256
    int k = idx >> 8, n = idx & 255;
    int col = (k < 256) ? ((k >> 6) * 320 + 256 + (k & 63)) : (1280 + (k - 256));
    g_Wk[idx] = W[n * 1536 + col];
}
__global__ void prep2_kernel(const float* __restrict__ W) {
    int idx = blockIdx.x * 256 + threadIdx.x;       // < 4*256*256
    int h = idx >> 16, n = (idx >> 8) & 255, k = idx & 255;
    float w = W[n * 1536 + h * 320 + k];
    __nv_bfloat16 hi = __float2bfloat16_rn(w);
    g_Bh[h][n][k] = hi;
    g_Bl[h][n][k] = __float2bfloat16_rn(w - __bfloat162float(hi));
}

// ---------- phase 1: FFMA2 GEMM + t==0 bf16 ring seed ----------
__global__ void __launch_bounds__(256) phase1_kernel(
    const float* __restrict__ o, const float* __restrict__ act,
    const float* __restrict__ bias, float* __restrict__ out)
{
    __shared__ __align__(16) float As[2][16 * 68];
    __shared__ __align__(16) float Bs[2][16 * 64];
    const int tid = threadIdx.x;
    const int colbase = blockIdx.x * 64;
    const int bt = blockIdx.y, b = bt >> 6, t = bt & 63;
    const int rg = tid >> 4, cg = tid & 15;

    unsigned long long acc[4][2];
    #pragma unroll
    for (int r = 0; r < 4; ++r) { acc[r][0] = 0ull; acc[r][1] = 0ull; }

    float ra[4], rb[4];
    const int akk = tid & 15, ar0 = tid >> 4;
    const int bcl = tid & 63, bkk = tid >> 6;

    auto loadChunk = [&](int cc) {
        const int kbase = cc * 16, k = kbase + akk;
        if (kbase < 256) {
            const int h = k >> 6, j = k & 63, ts = t - 4 + h;
            if (ts >= 0) {
                const float* base = act + (b * 64 + ts) * 4096 + j;
                #pragma unroll
                for (int q = 0; q < 4; ++q) ra[q] = base[(ar0 + q * 16) * 64];
            } else {
                #pragma unroll
                for (int q = 0; q < 4; ++q) ra[q] = 0.f;
            }
        } else {
            const float* base = o + (b * 64 + t) * 16384 + (k - 256);
            #pragma unroll
            for (int q = 0; q < 4; ++q) ra[q] = base[(ar0 + q * 16) * 256];
        }
        const float* wb = g_Wk + (kbase + bkk) * 256 + colbase + bcl;
        #pragma unroll
        for (int q = 0; q < 4; ++q) rb[q] = wb[q * 4 * 256];
    };
    auto stsChunk = [&](int buf) {
        #pragma unroll
        for (int q = 0; q < 4; ++q) As[buf][akk * 68 + ar0 + q * 16] = ra[q];
        #pragma unroll
        for (int q = 0; q < 4; ++q) Bs[buf][(bkk + q * 4) * 64 + bcl] = rb[q];
    };
    auto compute = [&](int buf) {
        #pragma unroll
        for (int kk = 0; kk < 16; ++kk) {
            const float4 a4 = *reinterpret_cast<const float4*>(&As[buf][kk * 68 + rg * 4]);
            const ulonglong2 bq = *reinterpret_cast<const ulonglong2*>(&Bs[buf][kk * 64 + cg * 4]);
            unsigned long long a0 = bcast2(a4.x), a1 = bcast2(a4.y);
            unsigned long long a2 = bcast2(a4.z), a3 = bcast2(a4.w);
            fma2(acc[0][0], a0, bq.x); fma2(acc[0][1], a0, bq.y);
            fma2(acc[1][0], a1, bq.x); fma2(acc[1][1], a1, bq.y);
            fma2(acc[2][0], a2, bq.x); fma2(acc[2][1], a2, bq.y);
            fma2(acc[3][0], a3, bq.x); fma2(acc[3][1], a3, bq.y);
        }
    };

    const int NC = 32;
    loadChunk(0); stsChunk(0);
    loadChunk(1);
    __syncthreads();
    for (int cc = 0; cc < NC; ++cc) {
        const int nb = (cc + 1) & 1;
        if (cc + 1 < NC) stsChunk(nb);
        if (cc + 2 < NC) loadChunk(cc + 2);
        compute(cc & 1);
        __syncthreads();
    }

    const int col = colbase + cg * 4;
    const float4 bv = *reinterpret_cast<const float4*>(&bias[col]);
    #pragma unroll
    for (int r = 0; r < 4; ++r) {
        float2 x0 = up2(acc[r][0]), x1 = up2(acc[r][1]);
        float4 ov = make_float4(x0.x + bv.x, x0.y + bv.y, x1.x + bv.z, x1.y + bv.w);
        const int row = rg * 4 + r;
        *reinterpret_cast<float4*>(&out[((b * 64 + t) * 64 + row) * 256 + col]) = ov;
        if (t == 0) {                               // seed bf16 ring slot 0
            const int rowg = b * 64 + row;
            float vv[4] = {ov.x, ov.y, ov.z, ov.w};
            #pragma unroll
            for (int i = 0; i < 4; ++i) {
                __nv_bfloat16 hv = __float2bfloat16_rn(vv[i]);
                g_zh[0][rowg][col + i] = hv;
                g_zl[0][rowg][col + i] = __float2bfloat16_rn(vv[i] - __bfloat162float(hv));
            }
        }
    }
}

// ---------- phase 2: warp-MMA bf16-split ----------
// Grid (4 Ntiles, 16 Mtiles) = 64 CTAs, 128 thr (2x2 warps, warp tile 32x32).
// K-panels of 64 double-buffered: Ah|Al|Bh|Bl each 64 rows x 144B (pad).
#define P2_STRIDE 144
#define P2_MAT    9216          // 64 * 144
#define P2_BUF    36864         // 4 matrices

__global__ void __launch_bounds__(128) phase2_mma(float* __restrict__ out, const int t)
{
    extern __shared__ __align__(16) char sm2[];
    const uint32_t sb = smem_u32(sm2);
    const int tid = threadIdx.x, warp = tid >> 5, lane = tid & 31;
    const int Nbase = blockIdx.x * 64;
    const int Mbase = blockIdx.y * 64;
    const int wm = warp >> 1, wn = warp & 1;

    const int h0 = (t >= 4) ? 0 : 4 - t;
    const int NC = 4 * (4 - h0);                    // K64 panels

    float acc[2][4][4];
    #pragma unroll
    for (int mi = 0; mi < 2; ++mi)
        #pragma unroll
        for (int ni = 0; ni < 4; ++ni)
            #pragma unroll
            for (int q = 0; q < 4; ++q) acc[mi][ni][q] = 0.f;

    auto load = [&](int c, int bb) {
        const int kc = h0 * 4 + c;
        const int h = kc >> 2, ts = t - 4 + h, k0 = (kc & 3) * 64;
        const uint32_t ab = sb + bb * P2_BUF;
        const char* sAh = (const char*)&g_zh[ts][Mbase][k0];
        const char* sAl = (const char*)&g_zl[ts][Mbase][k0];
        const char* sBh = (const char*)&g_Bh[h][Nbase][k0];
        const char* sBl = (const char*)&g_Bl[h][Nbase][k0];
        #pragma unroll
        for (int i = 0; i < 4; ++i) {               // 64 rows x 8 x 16B per matrix
            const int id = i * 128 + tid;
            const int row = id >> 3, cq = (id & 7) * 16;
            const uint32_t d = ab + row * P2_STRIDE + cq;
            const int gsrc = row * 512 + cq;        // global row stride 256 bf16
            cp16(d,              sAh + gsrc);
            cp16(d + P2_MAT,     sAl + gsrc);
            cp16(d + 2 * P2_MAT, sBh + gsrc);
            cp16(d + 3 * P2_MAT, sBl + gsrc);
        }
        cp_commit();
    };

    // ldmatrix lane addressing: lanes 0-15 -> rows, lanes 16-31 -> +16B (k8-15)
    const uint32_t rsel = (uint32_t)((lane & 15) * P2_STRIDE + (lane >> 4) * 16);

    load(0, 0);
    for (int c = 0; c < NC; ++c) {
        const int bb = c & 1;
        if (c + 1 < NC) { load(c + 1, bb ^ 1); cp_wait<1>(); }
        else             cp_wait<0>();
        __syncthreads();

        const uint32_t ab  = sb + bb * P2_BUF;
        const uint32_t aA0 = ab + (wm * 32) * P2_STRIDE + rsel;
        const uint32_t aB0 = ab + 2 * P2_MAT + (wn * 32) * P2_STRIDE + rsel;
        #pragma unroll
        for (int s = 0; s < 4; ++s) {               // 4 x K16 per panel
            const uint32_t off = s * 32;
            uint32_t ah[2][4], al[2][4], bh[2][4], bl[2][4];
            ldx4(ah[0], aA0 + off);
            ldx4(ah[1], aA0 + 16 * P2_STRIDE + off);
            ldx4(al[0], aA0 + P2_MAT + off);
            ldx4(al[1], aA0 + P2_MAT + 16 * P2_STRIDE + off);
            ldx4(bh[0], aB0 + off);
            ldx4(bh[1], aB0 + 16 * P2_STRIDE + off);
            ldx4(bl[0], aB0 + P2_MAT + off);
            ldx4(bl[1], aB0 + P2_MAT + 16 * P2_STRIDE + off);
            #pragma unroll
            for (int mi = 0; mi < 2; ++mi)
                #pragma unroll
                for (int ni = 0; ni < 4; ++ni) {
                    // FIXED pairing: b0 = k0-7 at n-octet, b1 = k8-15 at SAME n-octet
                    const uint32_t B0h = bh[ni >> 1][ni & 1];
                    const uint32_t B1h = bh[ni >> 1][(ni & 1) + 2];
                    const uint32_t B0l = bl[ni >> 1][ni & 1];
                    const uint32_t B1l = bl[ni >> 1][(ni & 1) + 2];
                    mma16816(acc[mi][ni], ah[mi], B0h, B1h);   // zh*Wh
                    mma16816(acc[mi][ni], al[mi], B0h, B1h);   // zl*Wh
                    mma16816(acc[mi][ni], ah[mi], B0l, B1l);   // zh*Wl
                }
        }
        __syncthreads();
    }

    // epilogue: out RMW (adds phase1 u_t) + bf16 ring write for step t
    const int r0b = Mbase + wm * 32 + (lane >> 2);
    const int cb  = Nbase + wn * 32 + (lane & 3) * 2;
    #pragma unroll
    for (int mi = 0; mi < 2; ++mi)
        #pragma unroll
        for (int ni = 0; ni < 4; ++ni)
            #pragma unroll
            for (int half = 0; half < 2; ++half) {
                const int r = r0b + mi * 16 + half * 8;
                const int cc = cb + ni * 8;
                const int b_ = r >> 6, p_ = r & 63;
                float* op = &out[((b_ * 64 + t) * 64 + p_) * 256 + cc];
                float2 cur = *reinterpret_cast<float2*>(op);
                const float v0 = cur.x + acc[mi][ni][half * 2];
                const float v1 = cur.y + acc[mi][ni][half * 2 + 1];
                *reinterpret_cast<float2*>(op) = make_float2(v0, v1);
                __nv_bfloat16 h0v = __float2bfloat16_rn(v0);
                __nv_bfloat16 h1v = __float2bfloat16_rn(v1);
                *reinterpret_cast<__nv_bfloat162*>(&g_zh[t][r][cc]) =
                    __nv_bfloat162(h0v, h1v);
                *reinterpret_cast<__nv_bfloat162*>(&g_zl[t][r][cc]) =
                    __nv_bfloat162(__float2bfloat16_rn(v0 - __bfloat162float(h0v)),
                                   __float2bfloat16_rn(v1 - __bfloat162float(h1v)));
            }
}

// ---------- launch ----------
extern "C" void kernel_launch(void* const* d_in, const int* in_sizes, int n_in,
                              void* d_out, int out_size)
{
    const float* o_in = (const float*)d_in[0];   // (16,64,64,256)
    const float* a_in = (const float*)d_in[1];   // (16,64,64,64)
    const float* W_in = (const float*)d_in[2];   // (256,1536)
    const float* b_in = (const float*)d_in[3];   // (256,)
    float* out = (float*)d_out;                  // (16,64,64,256)

    cudaFuncSetAttribute(phase2_mma, cudaFuncAttributeMaxDynamicSharedMemorySize,
                         2 * P2_BUF);
    prep_kernel<<<512, 256>>>(W_in);
    prep2_kernel<<<1024, 256>>>(W_in);
    phase1_kernel<<<dim3(4, 1024), 256>>>(o_in, a_in, b_in, out);
    for (int t = 1; t < 64; ++t)
        phase2_mma<<<dim3(4, 16), 128, 2 * P2_BUF>>>(out, t);
}

// round 11
// speedup vs baseline: 1.3418x; 1.2928x over previous
#include <cuda_runtime.h>
#include <cuda_bf16.h>
#include <cstdint>

// ============================================================================
// HistCausalEncoder: B=16,T=64,P=64,IN=256,ACT=64,OUT=256,H=4
// phase1 (HMMA bf16-split): z = b + [a-hist|o] @ Wk    (dense GEMM 65536x256 K=512)
// phase2 (HMMA bf16-split): z += sum_h Wz_h*z_{t-4+h}  (63 sequential launches)
// All GEMMs: 3-term split Xh*Wh + Xl*Wh + Xh*Wl, fp32 accum, mma.sync.m16n8k16.
// z kept as bf16 hi/lo ring (g_zh/g_zl); phase1 epilogue seeds slot t=0.
// R11 vs R10: phase2 was latency-bound (occ 6%, tensor 4.7%) -> 8 warps +
// 4-stage pipeline; phase1 FFMA2 (smem-wall 505us) -> HMMA on packed X.
// ============================================================================

__device__ __align__(256) __nv_bfloat16 g_Bh[4][256][256];   // Wz hi [h][n][k]
__device__ __align__(256) __nv_bfloat16 g_Bl[4][256][256];   // Wz lo
__device__ __align__(256) __nv_bfloat16 g_Kh[256 * 512];     // phase1 W hi [n][k]
__device__ __align__(256) __nv_bfloat16 g_Kl[256 * 512];     // phase1 W lo
__device__ __align__(256) __nv_bfloat16 g_Xh[65536ull * 512];// packed input hi [row][k]
__device__ __align__(256) __nv_bfloat16 g_Xl[65536ull * 512];// packed input lo
__device__ __align__(256) __nv_bfloat16 g_zh[64][1024][256]; // z hi [t][b*64+p][c]
__device__ __align__(256) __nv_bfloat16 g_zl[64][1024][256]; // z lo

// ---------- helpers ----------
__device__ __forceinline__ uint32_t smem_u32(const void* p) {
    uint32_t a;
    asm("{ .reg .u64 t; cvta.to.shared.u64 t, %1; cvt.u32.u64 %0, t; }" : "=r"(a) : "l"(p));
    return a;
}
__device__ __forceinline__ void cp16(uint32_t dst, const void* src) {
    asm volatile("cp.async.cg.shared.global [%0], [%1], 16;" :: "r"(dst), "l"(src) : "memory");
}
__device__ __forceinline__ void cp_commit() { asm volatile("cp.async.commit_group;" ::: "memory"); }
template <int N> __device__ __forceinline__ void cp_wait() {
    asm volatile("cp.async.wait_group %0;" :: "n"(N) : "memory");
}
__device__ __forceinline__ void ldx4(uint32_t (&r)[4], uint32_t a) {
    asm volatile("ldmatrix.sync.aligned.m8n8.x4.shared.b16 {%0,%1,%2,%3}, [%4];"
                 : "=r"(r[0]), "=r"(r[1]), "=r"(r[2]), "=r"(r[3]) : "r"(a));
}
__device__ __forceinline__ void mma16816(float (&d)[4], const uint32_t (&a)[4],
                                         uint32_t b0, uint32_t b1) {
    asm volatile("mma.sync.aligned.m16n8k16.row.col.f32.bf16.bf16.f32 "
                 "{%0,%1,%2,%3}, {%4,%5,%6,%7}, {%8,%9}, {%0,%1,%2,%3};"
                 : "+f"(d[0]), "+f"(d[1]), "+f"(d[2]), "+f"(d[3])
                 : "r"(a[0]), "r"(a[1]), "r"(a[2]), "r"(a[3]), "r"(b0), "r"(b1));
}
__device__ __forceinline__ void splitbf(float v, __nv_bfloat16& hi, __nv_bfloat16& lo) {
    hi = __float2bfloat16_rn(v);
    lo = __float2bfloat16_rn(v - __bfloat162float(hi));
}

// ---------- prep: split weights ----------
__global__ void prepW_kernel(const float* __restrict__ W) {
    int idx = blockIdx.x * 256 + threadIdx.x;        // < 262144 + 131072
    if (idx < 4 * 256 * 256) {                       // phase2 Wz [h][n][k]
        int h = idx >> 16, n = (idx >> 8) & 255, k = idx & 255;
        splitbf(W[n * 1536 + h * 320 + k], g_Bh[h][n][k], g_Bl[h][n][k]);
    } else {                                         // phase1 Wk [n][k=512]
        int j = idx - 262144;
        int n = j >> 9, k = j & 511;
        int col = (k < 256) ? ((k >> 6) * 320 + 256 + (k & 63)) : (1280 + (k - 256));
        splitbf(W[n * 1536 + col], g_Kh[j], g_Kl[j]);
    }
}

// ---------- prep: pack X = [a_{t-4..t-1} | o_t] as bf16 hi/lo ----------
__global__ void prepX_kernel(const float* __restrict__ o, const float* __restrict__ act) {
    unsigned idx = blockIdx.x * 256 + threadIdx.x;   // < 65536*512
    int row = idx >> 9, k = idx & 511;
    int b = row >> 12, t = (row >> 6) & 63, p = row & 63;
    float v;
    if (k < 256) {
        int h = k >> 6, ts = t - 4 + h;
        v = (ts >= 0) ? act[((b * 64 + ts) * 64 + p) * 64 + (k & 63)] : 0.f;
    } else {
        v = o[(unsigned)row * 256 + (k - 256)];
    }
    splitbf(v, g_Xh[idx], g_Xl[idx]);
}

// ============================================================================
// phase 1: dense HMMA GEMM  out[65536,256] = X[65536,512] @ Wk^T + bias
// CTA tile 128x128, 256 thr (8 warps 4Mx2N, warp tile 32x64), 3-stage pipeline.
// ============================================================================
#define P1_STRIDE 144
#define P1_AMAT   18432          // 128*144
#define P1_BUF    73728          // Ah|Al|Bh|Bl per stage
#define P1_STAGES 3

__global__ void __launch_bounds__(256) phase1_mma(
    const float* __restrict__ bias, float* __restrict__ out)
{
    extern __shared__ __align__(16) char sm1[];
    const uint32_t sb = smem_u32(sm1);
    const int tid = threadIdx.x, warp = tid >> 5, lane = tid & 31;
    const int Nbase = blockIdx.x * 128;
    const int Mbase = blockIdx.y * 128;
    const int wm = warp >> 1, wn = warp & 1;

    float acc[2][8][4];
    #pragma unroll
    for (int mi = 0; mi < 2; ++mi)
        #pragma unroll
        for (int ni = 0; ni < 8; ++ni)
            #pragma unroll
            for (int q = 0; q < 4; ++q) acc[mi][ni][q] = 0.f;

    auto load = [&](int c, int st) {
        const int k0 = c * 64;
        const uint32_t ab = sb + st * P1_BUF;
        const char* xh = (const char*)g_Xh + (size_t)Mbase * 1024 + k0 * 2;
        const char* xl = (const char*)g_Xl + (size_t)Mbase * 1024 + k0 * 2;
        const char* kh = (const char*)g_Kh + (size_t)Nbase * 1024 + k0 * 2;
        const char* kl = (const char*)g_Kl + (size_t)Nbase * 1024 + k0 * 2;
        #pragma unroll
        for (int i = 0; i < 4; ++i) {               // 128 rows x 8 x 16B
            const int id = i * 256 + tid;
            const int row = id >> 3, cq = (id & 7) * 16;
            const uint32_t d = ab + row * P1_STRIDE + cq;
            const size_t g = (size_t)row * 1024 + cq;
            cp16(d,                xh + g);
            cp16(d + P1_AMAT,      xl + g);
            cp16(d + 2 * P1_AMAT,  kh + g);
            cp16(d + 3 * P1_AMAT,  kl + g);
        }
        cp_commit();
    };

    const uint32_t rsel = (uint32_t)((lane & 15) * P1_STRIDE + (lane >> 4) * 16);

    load(0, 0); load(1, 1);
    for (int c = 0; c < 8; ++c) {                   // K=512 -> 8 panels
        cp_wait<1>();
        __syncthreads();
        const int st = c % 3;
        const uint32_t ab  = sb + st * P1_BUF;
        const uint32_t aA0 = ab + (wm * 32) * P1_STRIDE + rsel;
        const uint32_t aB0 = ab + 2 * P1_AMAT + (wn * 64) * P1_STRIDE + rsel;
        #pragma unroll
        for (int s = 0; s < 4; ++s) {
            const uint32_t off = s * 32;
            uint32_t ah[2][4], al[2][4], bh[4][4], bl[4][4];
            ldx4(ah[0], aA0 + off);
            ldx4(ah[1], aA0 + 16 * P1_STRIDE + off);
            ldx4(al[0], aA0 + P1_AMAT + off);
            ldx4(al[1], aA0 + P1_AMAT + 16 * P1_STRIDE + off);
            #pragma unroll
            for (int j = 0; j < 4; ++j) {
                ldx4(bh[j], aB0 + j * 16 * P1_STRIDE + off);
                ldx4(bl[j], aB0 + P1_AMAT + j * 16 * P1_STRIDE + off);
            }
            #pragma unroll
            for (int mi = 0; mi < 2; ++mi)
                #pragma unroll
                for (int ni = 0; ni < 8; ++ni) {
                    const int nb = ni >> 1, sel = ni & 1;
                    const uint32_t B0h = bh[nb][sel], B1h = bh[nb][sel + 2];
                    const uint32_t B0l = bl[nb][sel], B1l = bl[nb][sel + 2];
                    mma16816(acc[mi][ni], ah[mi], B0h, B1h);
                    mma16816(acc[mi][ni], al[mi], B0h, B1h);
                    mma16816(acc[mi][ni], ah[mi], B0l, B1l);
                }
        }
        __syncthreads();
        if (c + 2 < 8) load(c + 2, (c + 2) % 3);
    }

    // epilogue: out = acc + bias; seed bf16 ring for t==0 rows
    const int r0 = Mbase + wm * 32 + (lane >> 2);
    const int cb = Nbase + wn * 64 + (lane & 3) * 2;
    #pragma unroll
    for (int mi = 0; mi < 2; ++mi)
        #pragma unroll
        for (int ni = 0; ni < 8; ++ni)
            #pragma unroll
            for (int half = 0; half < 2; ++half) {
                const int r = r0 + mi * 16 + half * 8;
                const int cc = cb + ni * 8;
                const float2 bv = *reinterpret_cast<const float2*>(&bias[cc]);
                const float v0 = acc[mi][ni][half * 2] + bv.x;
                const float v1 = acc[mi][ni][half * 2 + 1] + bv.y;
                *reinterpret_cast<float2*>(&out[(size_t)r * 256 + cc]) = make_float2(v0, v1);
                if (((r >> 6) & 63) == 0) {         // t == 0
                    const int rowg = (r >> 12) * 64 + (r & 63);
                    __nv_bfloat16 h0, l0, h1, l1;
                    splitbf(v0, h0, l0); splitbf(v1, h1, l1);
                    *reinterpret_cast<__nv_bfloat162*>(&g_zh[0][rowg][cc]) = __nv_bfloat162(h0, h1);
                    *reinterpret_cast<__nv_bfloat162*>(&g_zl[0][rowg][cc]) = __nv_bfloat162(l0, l1);
                }
            }
}

// ============================================================================
// phase 2 (per t): out[:,t,:,:] += Zhist @ Wz   (M=1024, N=256, K<=1024)
// Grid (4 Ntiles, 16 Mtiles) = 64 CTAs, 256 thr (8 warps 4Mx2N, tile 16x32),
// 4-stage cp.async pipeline over K64 panels.
// ============================================================================
#define P2_STRIDE 144
#define P2_MAT    9216           // 64*144
#define P2_BUF    36864          // Ah|Al|Bh|Bl per stage
#define P2_STAGES 4

__global__ void __launch_bounds__(256) phase2_mma(float* __restrict__ out, const int t)
{
    extern __shared__ __align__(16) char sm2[];
    const uint32_t sb = smem_u32(sm2);
    const int tid = threadIdx.x, warp = tid >> 5, lane = tid & 31;
    const int Nbase = blockIdx.x * 64;
    const int Mbase = blockIdx.y * 64;
    const int wm = warp >> 1, wn = warp & 1;

    const int h0 = (t >= 4) ? 0 : 4 - t;
    const int NC = 4 * (4 - h0);                    // K64 panels

    float acc[4][4];
    #pragma unroll
    for (int ni = 0; ni < 4; ++ni)
        #pragma unroll
        for (int q = 0; q < 4; ++q) acc[ni][q] = 0.f;

    auto load = [&](int c, int st) {
        const int kc = h0 * 4 + c;
        const int h = kc >> 2, ts = t - 4 + h, k0 = (kc & 3) * 64;
        const uint32_t ab = sb + st * P2_BUF;
        const char* sAh = (const char*)&g_zh[ts][Mbase][k0];
        const char* sAl = (const char*)&g_zl[ts][Mbase][k0];
        const char* sBh = (const char*)&g_Bh[h][Nbase][k0];
        const char* sBl = (const char*)&g_Bl[h][Nbase][k0];
        #pragma unroll
        for (int i = 0; i < 2; ++i) {               // 64 rows x 8 x 16B
            const int id = i * 256 + tid;
            const int row = id >> 3, cq = (id & 7) * 16;
            const uint32_t d = ab + row * P2_STRIDE + cq;
            const int g = row * 512 + cq;           // global row stride 256 bf16
            cp16(d,              sAh + g);
            cp16(d + P2_MAT,     sAl + g);
            cp16(d + 2 * P2_MAT, sBh + g);
            cp16(d + 3 * P2_MAT, sBl + g);
        }
        cp_commit();
    };

    const uint32_t rsel = (uint32_t)((lane & 15) * P2_STRIDE + (lane >> 4) * 16);

    load(0, 0); load(1, 1); load(2, 2);
    for (int c = 0; c < NC; ++c) {
        cp_wait<2>();
        __syncthreads();
        const int st = c & 3;
        const uint32_t ab  = sb + st * P2_BUF;
        const uint32_t aA0 = ab + (wm * 16) * P2_STRIDE + rsel;
        const uint32_t aB0 = ab + 2 * P2_MAT + (wn * 32) * P2_STRIDE + rsel;
        #pragma unroll
        for (int s = 0; s < 4; ++s) {
            const uint32_t off = s * 32;
            uint32_t ah[4], al[4], bh[2][4], bl[2][4];
            ldx4(ah, aA0 + off);
            ldx4(al, aA0 + P2_MAT + off);
            ldx4(bh[0], aB0 + off);
            ldx4(bh[1], aB0 + 16 * P2_STRIDE + off);
            ldx4(bl[0], aB0 + P2_MAT + off);
            ldx4(bl[1], aB0 + P2_MAT + 16 * P2_STRIDE + off);
            #pragma unroll
            for (int ni = 0; ni < 4; ++ni) {
                const int nb = ni >> 1, sel = ni & 1;
                const uint32_t B0h = bh[nb][sel], B1h = bh[nb][sel + 2];
                const uint32_t B0l = bl[nb][sel], B1l = bl[nb][sel + 2];
                mma16816(acc[ni], ah, B0h, B1h);    // zh*Wh
                mma16816(acc[ni], al, B0h, B1h);    // zl*Wh
                mma16816(acc[ni], ah, B0l, B1l);    // zh*Wl
            }
        }
        __syncthreads();
        if (c + 3 < NC) load(c + 3, (c + 3) & 3);
    }

    // epilogue: out RMW (adds phase1 u_t) + bf16 ring write for step t
    const int r0 = Mbase + wm * 16 + (lane >> 2);
    const int cb = Nbase + wn * 32 + (lane & 3) * 2;
    #pragma unroll
    for (int ni = 0; ni < 4; ++ni)
        #pragma unroll
        for (int half = 0; half < 2; ++half) {
            const int r = r0 + half * 8;
            const int cc = cb + ni * 8;
            const int b_ = r >> 6, p_ = r & 63;
            float* op = &out[((b_ * 64 + t) * 64 + p_) * 256 + cc];
            float2 cur = *reinterpret_cast<float2*>(op);
            const float v0 = cur.x + acc[ni][half * 2];
            const float v1 = cur.y + acc[ni][half * 2 + 1];
            *reinterpret_cast<float2*>(op) = make_float2(v0, v1);
            __nv_bfloat16 h0, l0, h1, l1;
            splitbf(v0, h0, l0); splitbf(v1, h1, l1);
            *reinterpret_cast<__nv_bfloat162*>(&g_zh[t][r][cc]) = __nv_bfloat162(h0, h1);
            *reinterpret_cast<__nv_bfloat162*>(&g_zl[t][r][cc]) = __nv_bfloat162(l0, l1);
        }
}

// ---------- launch ----------
extern "C" void kernel_launch(void* const* d_in, const int* in_sizes, int n_in,
                              void* d_out, int out_size)
{
    const float* o_in = (const float*)d_in[0];   // (16,64,64,256)
    const float* a_in = (const float*)d_in[1];   // (16,64,64,64)
    const float* W_in = (const float*)d_in[2];   // (256,1536)
    const float* b_in = (const float*)d_in[3];   // (256,)
    float* out = (float*)d_out;                  // (16,64,64,256)

    cudaFuncSetAttribute(phase1_mma, cudaFuncAttributeMaxDynamicSharedMemorySize,
                         P1_STAGES * P1_BUF);
    cudaFuncSetAttribute(phase2_mma, cudaFuncAttributeMaxDynamicSharedMemorySize,
                         P2_STAGES * P2_BUF);

    prepW_kernel<<<1536, 256>>>(W_in);
    prepX_kernel<<<131072, 256>>>(o_in, a_in);
    phase1_mma<<<dim3(2, 512), 256, P1_STAGES * P1_BUF>>>(b_in, out);
    for (int t = 1; t < 64; ++t)
        phase2_mma<<<dim3(4, 16), 256, P2_STAGES * P2_BUF>>>(out, t);
}

// round 12
// speedup vs baseline: 1.9340x; 1.4413x over previous
#include <cuda_runtime.h>
#include <cuda_bf16.h>
#include <cstdint>

// ============================================================================
// HistCausalEncoder: B=16,T=64,P=64,IN=256,ACT=64,OUT=256,H=4
// phase1 (HMMA): u = b + [a-hist|o] @ Wk          (dense, parallel)
// vpass  (HMMA): out[t'] += W3 @ u[t'-1], t' even (parallel, 2-step cross term)
// pairs  (HMMA): z_t     = u-acc + sum W_h z_hist   (group0)
//                z_{t+1} = v-acc + sum G_h z_hist   (group1, G = unrolled)
//   -> 31 pair launches + 1 final = 32 sequential launches (was 63).
// All GEMMs: 3-term bf16 split Xh*Wh + Xl*Wh + Xh*Wl, fp32 accum, mma.sync.
// ============================================================================

__device__ __align__(256) __nv_bfloat16 g_Bh[4][256][256];   // Wz hi [h][n][k]
__device__ __align__(256) __nv_bfloat16 g_Bl[4][256][256];   // Wz lo
__device__ __align__(256) __nv_bfloat16 g_Gh[4][256][256];   // 2-step G hi
__device__ __align__(256) __nv_bfloat16 g_Gl[4][256][256];   // 2-step G lo
__device__ __align__(256) __nv_bfloat16 g_Kh[256 * 512];     // phase1 W hi [n][k]
__device__ __align__(256) __nv_bfloat16 g_Kl[256 * 512];     // phase1 W lo
__device__ __align__(256) __nv_bfloat16 g_Xh[65536ull * 512];// packed input hi
__device__ __align__(256) __nv_bfloat16 g_Xl[65536ull * 512];// packed input lo
__device__ __align__(256) __nv_bfloat16 g_uh[32][1024][256]; // u (odd t) hi
__device__ __align__(256) __nv_bfloat16 g_ul[32][1024][256]; // u (odd t) lo
__device__ __align__(256) __nv_bfloat16 g_zh[64][1024][256]; // z hi [t][b*64+p][c]
__device__ __align__(256) __nv_bfloat16 g_zl[64][1024][256]; // z lo

// ---------- helpers ----------
__device__ __forceinline__ uint32_t smem_u32(const void* p) {
    uint32_t a;
    asm("{ .reg .u64 t; cvta.to.shared.u64 t, %1; cvt.u32.u64 %0, t; }" : "=r"(a) : "l"(p));
    return a;
}
__device__ __forceinline__ void cp16(uint32_t dst, const void* src) {
    asm volatile("cp.async.cg.shared.global [%0], [%1], 16;" :: "r"(dst), "l"(src) : "memory");
}
__device__ __forceinline__ void cp_commit() { asm volatile("cp.async.commit_group;" ::: "memory"); }
template <int N> __device__ __forceinline__ void cp_wait() {
    asm volatile("cp.async.wait_group %0;" :: "n"(N) : "memory");
}
__device__ __forceinline__ void ldx4(uint32_t (&r)[4], uint32_t a) {
    asm volatile("ldmatrix.sync.aligned.m8n8.x4.shared.b16 {%0,%1,%2,%3}, [%4];"
                 : "=r"(r[0]), "=r"(r[1]), "=r"(r[2]), "=r"(r[3]) : "r"(a));
}
__device__ __forceinline__ void mma16816(float (&d)[4], const uint32_t (&a)[4],
                                         uint32_t b0, uint32_t b1) {
    asm volatile("mma.sync.aligned.m16n8k16.row.col.f32.bf16.bf16.f32 "
                 "{%0,%1,%2,%3}, {%4,%5,%6,%7}, {%8,%9}, {%0,%1,%2,%3};"
                 : "+f"(d[0]), "+f"(d[1]), "+f"(d[2]), "+f"(d[3])
                 : "r"(a[0]), "r"(a[1]), "r"(a[2]), "r"(a[3]), "r"(b0), "r"(b1));
}
__device__ __forceinline__ void splitbf(float v, __nv_bfloat16& hi, __nv_bfloat16& lo) {
    hi = __float2bfloat16_rn(v);
    lo = __float2bfloat16_rn(v - __bfloat162float(hi));
}

// ---------- prep: split weights ----------
__global__ void prepW_kernel(const float* __restrict__ W) {
    int idx = blockIdx.x * 256 + threadIdx.x;        // < 262144 + 131072
    if (idx < 4 * 256 * 256) {                       // phase2 Wz [h][n][k]
        int h = idx >> 16, n = (idx >> 8) & 255, k = idx & 255;
        splitbf(W[n * 1536 + h * 320 + k], g_Bh[h][n][k], g_Bl[h][n][k]);
    } else {                                         // phase1 Wk [n][k=512]
        int j = idx - 262144;
        int n = j >> 9, k = j & 511;
        int col = (k < 256) ? ((k >> 6) * 320 + 256 + (k & 63)) : (1280 + (k - 256));
        splitbf(W[n * 1536 + col], g_Kh[j], g_Kl[j]);
    }
}

// ---------- prep: 2-step unrolled weights G_h = W_{h-1} + W3 @ W_h ----------
__global__ void prepG_kernel(const float* __restrict__ W) {
    int idx = blockIdx.x * 256 + threadIdx.x;        // < 4*256*256
    int h = idx >> 16, n = (idx >> 8) & 255, k = idx & 255;
    float acc = (h > 0) ? W[n * 1536 + (h - 1) * 320 + k] : 0.f;
    const float* w3row = W + n * 1536 + 960;         // W3[n][.]
    for (int m = 0; m < 256; ++m)
        acc += w3row[m] * W[m * 1536 + h * 320 + k]; // (W3 @ W_h)[n][k]
    splitbf(acc, g_Gh[h][n][k], g_Gl[h][n][k]);
}

// ---------- prep: pack X = [a_{t-4..t-1} | o_t] as bf16 hi/lo ----------
__global__ void prepX_kernel(const float* __restrict__ o, const float* __restrict__ act) {
    unsigned idx = blockIdx.x * 256 + threadIdx.x;   // < 65536*512
    int row = idx >> 9, k = idx & 511;
    int b = row >> 12, t = (row >> 6) & 63, p = row & 63;
    float v;
    if (k < 256) {
        int h = k >> 6, ts = t - 4 + h;
        v = (ts >= 0) ? act[((b * 64 + ts) * 64 + p) * 64 + (k & 63)] : 0.f;
    } else {
        v = o[(unsigned)row * 256 + (k - 256)];
    }
    splitbf(v, g_Xh[idx], g_Xl[idx]);
}

// ============================================================================
// phase 1: dense HMMA GEMM  out[65536,256] = X[65536,512] @ Wk^T + bias
// CTA tile 128x128, 256 thr (8 warps 4Mx2N, warp tile 32x64), 3-stage pipeline.
// Epilogue also: seed bf16 ring t=0; store split u for odd t (vpass operand).
// ============================================================================
#define P1_STRIDE 144
#define P1_AMAT   18432          // 128*144
#define P1_BUF    73728
#define P1_STAGES 3

__global__ void __launch_bounds__(256) phase1_mma(
    const float* __restrict__ bias, float* __restrict__ out)
{
    extern __shared__ __align__(16) char sm1[];
    const uint32_t sb = smem_u32(sm1);
    const int tid = threadIdx.x, warp = tid >> 5, lane = tid & 31;
    const int Nbase = blockIdx.x * 128;
    const int Mbase = blockIdx.y * 128;
    const int wm = warp >> 1, wn = warp & 1;

    float acc[2][8][4];
    #pragma unroll
    for (int mi = 0; mi < 2; ++mi)
        #pragma unroll
        for (int ni = 0; ni < 8; ++ni)
            #pragma unroll
            for (int q = 0; q < 4; ++q) acc[mi][ni][q] = 0.f;

    auto load = [&](int c, int st) {
        const int k0 = c * 64;
        const uint32_t ab = sb + st * P1_BUF;
        const char* xh = (const char*)g_Xh + (size_t)Mbase * 1024 + k0 * 2;
        const char* xl = (const char*)g_Xl + (size_t)Mbase * 1024 + k0 * 2;
        const char* kh = (const char*)g_Kh + (size_t)Nbase * 1024 + k0 * 2;
        const char* kl = (const char*)g_Kl + (size_t)Nbase * 1024 + k0 * 2;
        #pragma unroll
        for (int i = 0; i < 4; ++i) {
            const int id = i * 256 + tid;
            const int row = id >> 3, cq = (id & 7) * 16;
            const uint32_t d = ab + row * P1_STRIDE + cq;
            const size_t g = (size_t)row * 1024 + cq;
            cp16(d,                xh + g);
            cp16(d + P1_AMAT,      xl + g);
            cp16(d + 2 * P1_AMAT,  kh + g);
            cp16(d + 3 * P1_AMAT,  kl + g);
        }
        cp_commit();
    };

    const uint32_t rsel = (uint32_t)((lane & 15) * P1_STRIDE + (lane >> 4) * 16);

    load(0, 0); load(1, 1);
    for (int c = 0; c < 8; ++c) {
        cp_wait<1>();
        __syncthreads();
        const int st = c % 3;
        const uint32_t ab  = sb + st * P1_BUF;
        const uint32_t aA0 = ab + (wm * 32) * P1_STRIDE + rsel;
        const uint32_t aB0 = ab + 2 * P1_AMAT + (wn * 64) * P1_STRIDE + rsel;
        #pragma unroll
        for (int s = 0; s < 4; ++s) {
            const uint32_t off = s * 32;
            uint32_t ah[2][4], al[2][4], bh[4][4], bl[4][4];
            ldx4(ah[0], aA0 + off);
            ldx4(ah[1], aA0 + 16 * P1_STRIDE + off);
            ldx4(al[0], aA0 + P1_AMAT + off);
            ldx4(al[1], aA0 + P1_AMAT + 16 * P1_STRIDE + off);
            #pragma unroll
            for (int j = 0; j < 4; ++j) {
                ldx4(bh[j], aB0 + j * 16 * P1_STRIDE + off);
                ldx4(bl[j], aB0 + P1_AMAT + j * 16 * P1_STRIDE + off);
            }
            #pragma unroll
            for (int mi = 0; mi < 2; ++mi)
                #pragma unroll
                for (int ni = 0; ni < 8; ++ni) {
                    const int nb = ni >> 1, sel = ni & 1;
                    const uint32_t B0h = bh[nb][sel], B1h = bh[nb][sel + 2];
                    const uint32_t B0l = bl[nb][sel], B1l = bl[nb][sel + 2];
                    mma16816(acc[mi][ni], ah[mi], B0h, B1h);
                    mma16816(acc[mi][ni], al[mi], B0h, B1h);
                    mma16816(acc[mi][ni], ah[mi], B0l, B1l);
                }
        }
        __syncthreads();
        if (c + 2 < 8) load(c + 2, (c + 2) % 3);
    }

    const int r0 = Mbase + wm * 32 + (lane >> 2);
    const int cb = Nbase + wn * 64 + (lane & 3) * 2;
    #pragma unroll
    for (int mi = 0; mi < 2; ++mi)
        #pragma unroll
        for (int ni = 0; ni < 8; ++ni)
            #pragma unroll
            for (int half = 0; half < 2; ++half) {
                const int r = r0 + mi * 16 + half * 8;
                const int cc = cb + ni * 8;
                const float2 bv = *reinterpret_cast<const float2*>(&bias[cc]);
                const float v0 = acc[mi][ni][half * 2] + bv.x;
                const float v1 = acc[mi][ni][half * 2 + 1] + bv.y;
                *reinterpret_cast<float2*>(&out[(size_t)r * 256 + cc]) = make_float2(v0, v1);
                const int t = (r >> 6) & 63;
                const int rowg = (r >> 12) * 64 + (r & 63);
                __nv_bfloat16 h0, l0, h1, l1;
                splitbf(v0, h0, l0); splitbf(v1, h1, l1);
                if (t == 0) {                        // seed z ring
                    *reinterpret_cast<__nv_bfloat162*>(&g_zh[0][rowg][cc]) = __nv_bfloat162(h0, h1);
                    *reinterpret_cast<__nv_bfloat162*>(&g_zl[0][rowg][cc]) = __nv_bfloat162(l0, l1);
                } else if (t & 1) {                  // store u for vpass
                    *reinterpret_cast<__nv_bfloat162*>(&g_uh[t >> 1][rowg][cc]) = __nv_bfloat162(h0, h1);
                    *reinterpret_cast<__nv_bfloat162*>(&g_ul[t >> 1][rowg][cc]) = __nv_bfloat162(l0, l1);
                }
            }
}

// ============================================================================
// Shared tile geometry for the 64x64 sequential/vpass kernels
// ============================================================================
#define P2_STRIDE 144
#define P2_MAT    9216           // 64*144
#define P2_BUF    36864          // Ah|Al|Bh|Bl per stage
#define P2_STAGES 4

// ---- vpass (parallel): out[:,2s+2,:,:] += u[:,2s+1,:,:] @ W3^T, s=0..30 ----
__global__ void __launch_bounds__(256) vpass_mma(float* __restrict__ out)
{
    extern __shared__ __align__(16) char smv[];
    const uint32_t sb = smem_u32(smv);
    const int tid = threadIdx.x, warp = tid >> 5, lane = tid & 31;
    const int Nbase = blockIdx.x * 64;
    const int Mbase = blockIdx.y * 64;
    const int slice = blockIdx.z;                   // 0..30, target t' = 2*slice+2
    const int tgt = 2 * slice + 2;

    float acc[4][4];
    #pragma unroll
    for (int ni = 0; ni < 4; ++ni)
        #pragma unroll
        for (int q = 0; q < 4; ++q) acc[ni][q] = 0.f;

    auto load = [&](int c, int st) {
        const int k0 = c * 64;
        const uint32_t ab = sb + st * P2_BUF;
        const char* sAh = (const char*)&g_uh[slice][Mbase][k0];
        const char* sAl = (const char*)&g_ul[slice][Mbase][k0];
        const char* sBh = (const char*)&g_Bh[3][Nbase][k0];
        const char* sBl = (const char*)&g_Bl[3][Nbase][k0];
        #pragma unroll
        for (int i = 0; i < 2; ++i) {
            const int id = i * 256 + tid;
            const int row = id >> 3, cq = (id & 7) * 16;
            const uint32_t d = ab + row * P2_STRIDE + cq;
            const int g = row * 512 + cq;
            cp16(d,              sAh + g);
            cp16(d + P2_MAT,     sAl + g);
            cp16(d + 2 * P2_MAT, sBh + g);
            cp16(d + 3 * P2_MAT, sBl + g);
        }
        cp_commit();
    };

    const uint32_t rsel = (uint32_t)((lane & 15) * P2_STRIDE + (lane >> 4) * 16);
    const int wm = warp >> 1, wn = warp & 1;

    load(0, 0); load(1, 1); load(2, 2);
    for (int c = 0; c < 4; ++c) {                   // K=256
        cp_wait<2>();
        __syncthreads();
        const uint32_t ab  = sb + (c & 3) * P2_BUF;
        const uint32_t aA0 = ab + (wm * 16) * P2_STRIDE + rsel;
        const uint32_t aB0 = ab + 2 * P2_MAT + (wn * 32) * P2_STRIDE + rsel;
        #pragma unroll
        for (int s = 0; s < 4; ++s) {
            const uint32_t off = s * 32;
            uint32_t ah[4], al[4], bh[2][4], bl[2][4];
            ldx4(ah, aA0 + off);
            ldx4(al, aA0 + P2_MAT + off);
            ldx4(bh[0], aB0 + off);
            ldx4(bh[1], aB0 + 16 * P2_STRIDE + off);
            ldx4(bl[0], aB0 + P2_MAT + off);
            ldx4(bl[1], aB0 + P2_MAT + 16 * P2_STRIDE + off);
            #pragma unroll
            for (int ni = 0; ni < 4; ++ni) {
                const int nb = ni >> 1, sel = ni & 1;
                mma16816(acc[ni], ah, bh[nb][sel], bh[nb][sel + 2]);
                mma16816(acc[ni], al, bh[nb][sel], bh[nb][sel + 2]);
                mma16816(acc[ni], ah, bl[nb][sel], bl[nb][sel + 2]);
            }
        }
        __syncthreads();
        if (c + 3 < 4) load(c + 3, (c + 3) & 3);
    }

    const int r0 = Mbase + wm * 16 + (lane >> 2);
    const int cb = Nbase + wn * 32 + (lane & 3) * 2;
    #pragma unroll
    for (int ni = 0; ni < 4; ++ni)
        #pragma unroll
        for (int half = 0; half < 2; ++half) {
            const int r = r0 + half * 8;
            const int cc = cb + ni * 8;
            const int b_ = r >> 6, p_ = r & 63;
            float* op = &out[((b_ * 64 + tgt) * 64 + p_) * 256 + cc];
            float2 cur = *reinterpret_cast<float2*>(op);
            cur.x += acc[ni][half * 2];
            cur.y += acc[ni][half * 2 + 1];
            *reinterpret_cast<float2*>(op) = cur;
        }
}

// ---- pair kernel (sequential): grp0 -> z_t (W), grp1 -> z_{t+1} (G) ----
__global__ void __launch_bounds__(256) pair_mma(float* __restrict__ out, const int t)
{
    extern __shared__ __align__(16) char sm2[];
    const uint32_t sb = smem_u32(sm2);
    const int tid = threadIdx.x, warp = tid >> 5, lane = tid & 31;
    const int Nbase = blockIdx.x * 64;
    const int grp = blockIdx.y >> 4;                // 0: step t, 1: step t+1
    const int Mbase = (blockIdx.y & 15) * 64;
    const int tOut = t + grp;
    const __nv_bfloat16 (*Wh)[256][256] = grp ? g_Gh : g_Bh;
    const __nv_bfloat16 (*Wl)[256][256] = grp ? g_Gl : g_Bl;
    const int wm = warp >> 1, wn = warp & 1;

    const int h0 = (t >= 4) ? 0 : 4 - t;
    const int NC = 4 * (4 - h0);

    float acc[4][4];
    #pragma unroll
    for (int ni = 0; ni < 4; ++ni)
        #pragma unroll
        for (int q = 0; q < 4; ++q) acc[ni][q] = 0.f;

    auto load = [&](int c, int st) {
        const int kc = h0 * 4 + c;
        const int h = kc >> 2, ts = t - 4 + h, k0 = (kc & 3) * 64;
        const uint32_t ab = sb + st * P2_BUF;
        const char* sAh = (const char*)&g_zh[ts][Mbase][k0];
        const char* sAl = (const char*)&g_zl[ts][Mbase][k0];
        const char* sBh = (const char*)&Wh[h][Nbase][k0];
        const char* sBl = (const char*)&Wl[h][Nbase][k0];
        #pragma unroll
        for (int i = 0; i < 2; ++i) {
            const int id = i * 256 + tid;
            const int row = id >> 3, cq = (id & 7) * 16;
            const uint32_t d = ab + row * P2_STRIDE + cq;
            const int g = row * 512 + cq;
            cp16(d,              sAh + g);
            cp16(d + P2_MAT,     sAl + g);
            cp16(d + 2 * P2_MAT, sBh + g);
            cp16(d + 3 * P2_MAT, sBl + g);
        }
        cp_commit();
    };

    const uint32_t rsel = (uint32_t)((lane & 15) * P2_STRIDE + (lane >> 4) * 16);

    load(0, 0); load(1, 1); load(2, 2);
    for (int c = 0; c < NC; ++c) {
        cp_wait<2>();
        __syncthreads();
        const int st = c & 3;
        const uint32_t ab  = sb + st * P2_BUF;
        const uint32_t aA0 = ab + (wm * 16) * P2_STRIDE + rsel;
        const uint32_t aB0 = ab + 2 * P2_MAT + (wn * 32) * P2_STRIDE + rsel;
        #pragma unroll
        for (int s = 0; s < 4; ++s) {
            const uint32_t off = s * 32;
            uint32_t ah[4], al[4], bh[2][4], bl[2][4];
            ldx4(ah, aA0 + off);
            ldx4(al, aA0 + P2_MAT + off);
            ldx4(bh[0], aB0 + off);
            ldx4(bh[1], aB0 + 16 * P2_STRIDE + off);
            ldx4(bl[0], aB0 + P2_MAT + off);
            ldx4(bl[1], aB0 + P2_MAT + 16 * P2_STRIDE + off);
            #pragma unroll
            for (int ni = 0; ni < 4; ++ni) {
                const int nb = ni >> 1, sel = ni & 1;
                mma16816(acc[ni], ah, bh[nb][sel], bh[nb][sel + 2]);
                mma16816(acc[ni], al, bh[nb][sel], bh[nb][sel + 2]);
                mma16816(acc[ni], ah, bl[nb][sel], bl[nb][sel + 2]);
            }
        }
        __syncthreads();
        if (c + 3 < NC) load(c + 3, (c + 3) & 3);
    }

    // epilogue: out RMW (u_t or v_{t+1} accumulator) + bf16 ring write
    const int r0 = Mbase + wm * 16 + (lane >> 2);
    const int cb = Nbase + wn * 32 + (lane & 3) * 2;
    #pragma unroll
    for (int ni = 0; ni < 4; ++ni)
        #pragma unroll
        for (int half = 0; half < 2; ++half) {
            const int r = r0 + half * 8;
            const int cc = cb + ni * 8;
            const int b_ = r >> 6, p_ = r & 63;
            float* op = &out[((b_ * 64 + tOut) * 64 + p_) * 256 + cc];
            float2 cur = *reinterpret_cast<float2*>(op);
            const float v0 = cur.x + acc[ni][half * 2];
            const float v1 = cur.y + acc[ni][half * 2 + 1];
            *reinterpret_cast<float2*>(op) = make_float2(v0, v1);
            __nv_bfloat16 h0, l0, h1, l1;
            splitbf(v0, h0, l0); splitbf(v1, h1, l1);
            *reinterpret_cast<__nv_bfloat162*>(&g_zh[tOut][r][cc]) = __nv_bfloat162(h0, h1);
            *reinterpret_cast<__nv_bfloat162*>(&g_zl[tOut][r][cc]) = __nv_bfloat162(l0, l1);
        }
}

// ---------- launch ----------
extern "C" void kernel_launch(void* const* d_in, const int* in_sizes, int n_in,
                              void* d_out, int out_size)
{
    const float* o_in = (const float*)d_in[0];   // (16,64,64,256)
    const float* a_in = (const float*)d_in[1];   // (16,64,64,64)
    const float* W_in = (const float*)d_in[2];   // (256,1536)
    const float* b_in = (const float*)d_in[3];   // (256,)
    float* out = (float*)d_out;                  // (16,64,64,256)

    cudaFuncSetAttribute(phase1_mma, cudaFuncAttributeMaxDynamicSharedMemorySize,
                         P1_STAGES * P1_BUF);
    cudaFuncSetAttribute(vpass_mma, cudaFuncAttributeMaxDynamicSharedMemorySize,
                         P2_STAGES * P2_BUF);
    cudaFuncSetAttribute(pair_mma, cudaFuncAttributeMaxDynamicSharedMemorySize,
                         P2_STAGES * P2_BUF);

    prepW_kernel<<<1536, 256>>>(W_in);
    prepG_kernel<<<1024, 256>>>(W_in);
    prepX_kernel<<<131072, 256>>>(o_in, a_in);
    phase1_mma<<<dim3(2, 512), 256, P1_STAGES * P1_BUF>>>(b_in, out);
    vpass_mma<<<dim3(4, 16, 31), 256, P2_STAGES * P2_BUF>>>(out);
    for (int t = 1; t < 63; t += 2)              // 31 pair launches (t, t+1)
        pair_mma<<<dim3(4, 32), 256, P2_STAGES * P2_BUF>>>(out, t);
    pair_mma<<<dim3(4, 16), 256, P2_STAGES * P2_BUF>>>(out, 63);  // grp0 only
}